// round 4
// baseline (speedup 1.0000x reference)
#include <cuda_runtime.h>
#include <cuda_bf16.h>

#define Nn 22
#define Fd 192
#define THREADS 192

typedef unsigned int u32;
typedef unsigned short u16;

// ---------------- SMEM layout (bytes) ----------------
#define OFF_ADJ  0                      // 484 f
#define OFF_AVS  1952                   // 1152 f (a1,a2,ao)
#define OFF_WS   6560                   // 2 * 1108 f per-batch scratch
#define XB       15424
#define OFF_AHI  (XB)                   // A hi: 48 x 216 bf16 (stride 432B)
#define OFF_ALO  (XB + 20736)
#define OFF_B1   (XB + 41472)           // 2 bufs x (hi 13824 + lo 13824)
#define OFF_HCHI (XB)                   // hc hi: 48 x 408 bf16 (stride 816B)
#define OFF_HCLO (XB + 39168)
#define YB       112192
#define OFF_WHS  (YB)                   // Wh fp32: 48 x 386
#define OFF_B2   (YB)                   // 2 bufs x 27648 (reuses whs region)
#define OFF_WHO  (YB + 55296)           // who fp32: 48 x 194
#define SMEM_TOTAL 204736

#define ASTR 432     // A/B row stride bytes (216 bf16)
#define HSTR 816     // hc row stride bytes (408 bf16)
#define WHS_S 386    // whs row stride floats
#define WHO_S 194    // who row stride floats

// ---- weight splits (device-global scratch: sanctioned path) ----
static __device__ __nv_bfloat16 g_w12t_hi[384*192];
static __device__ __nv_bfloat16 g_w12t_lo[384*192];
static __device__ __nv_bfloat16 g_wot_hi[192*384];
static __device__ __nv_bfloat16 g_wot_lo[192*384];

// ---------------- helpers ----------------
__device__ __forceinline__ u32 smem_u32(const void* p){
    u32 a;
    asm("{ .reg .u64 t; cvta.to.shared.u64 t, %1; cvt.u32.u64 %0, t; }" : "=r"(a) : "l"(p));
    return a;
}
__device__ __forceinline__ void split_bf16(float v, u16& h, u16& l){
    __nv_bfloat16 hb = __float2bfloat16(v);
    float hf = __bfloat162float(hb);
    __nv_bfloat16 lb = __float2bfloat16(v - hf);
    h = __bfloat16_as_ushort(hb);
    l = __bfloat16_as_ushort(lb);
}
__device__ __forceinline__ float elu1(float v){ return (v > 0.0f) ? v : (__expf(v) - 1.0f); }

#define CPA16(sa, g) asm volatile("cp.async.cg.shared.global [%0], [%1], 16;" :: "r"((u32)(sa)), "l"(g) : "memory")
#define CPC()  asm volatile("cp.async.commit_group;" ::: "memory")
#define CPW1() asm volatile("cp.async.wait_group 1;" ::: "memory")
#define CPW0() asm volatile("cp.async.wait_group 0;" ::: "memory")

__device__ __forceinline__ void mma_bf16(float* c, u32 a0,u32 a1,u32 a2,u32 a3, u32 b0,u32 b1){
    asm volatile("mma.sync.aligned.m16n8k16.row.col.f32.bf16.bf16.f32 "
        "{%0,%1,%2,%3}, {%4,%5,%6,%7}, {%8,%9}, {%0,%1,%2,%3};"
        : "+f"(c[0]),"+f"(c[1]),"+f"(c[2]),"+f"(c[3])
        : "r"(a0),"r"(a1),"r"(a2),"r"(a3),"r"(b0),"r"(b1));
}

// softmax over 22 nodes; lane i handles row i; attw stride 23
__device__ __forceinline__ void warp_softmax(const float* __restrict__ ev, const float* __restrict__ adjs,
                                             float* __restrict__ attw, int lane)
{
    if (lane < Nn) {
        int i = lane;
        float esrc = ev[i];
        float vals[Nn];
        float mx = -1e30f;
#pragma unroll
        for (int j = 0; j < Nn; j++) {
            if (adjs[i * Nn + j] != 0.0f) {
                float v = esrc + ev[Nn + j];
                v = (v > 0.0f) ? v : 0.2f * v;
                vals[j] = v;
                mx = fmaxf(mx, v);
            } else vals[j] = -1e30f;
        }
        float ssum = 0.0f;
#pragma unroll
        for (int j = 0; j < Nn; j++) {
            float e = (vals[j] > -1e29f) ? __expf(vals[j] - mx) : 0.0f;
            vals[j] = e; ssum += e;
        }
        float inv = 1.0f / ssum;
#pragma unroll
        for (int j = 0; j < Nn; j++) attw[i * 23 + j] = vals[j] * inv;
    }
}

// chunk loader: 32 n-rows x 192 k bf16 (hi+lo) -> smem buf via cp.async
__device__ __forceinline__ void issue_chunk(u32 sbuf, const __nv_bfloat16* srch,
                                            const __nv_bfloat16* srcl, int tid, int gstride)
{
#pragma unroll
    for (int q = 0; q < 4; q++) {
        int lin = tid + 192 * q;
        int r = lin / 24, k8 = (lin % 24) * 8;
        CPA16(sbuf + r * ASTR + k8 * 2,          srch + r * gstride + k8);
        CPA16(sbuf + 13824 + r * ASTR + k8 * 2,  srcl + r * gstride + k8);
    }
}

// ================= prep: split weights, transposed (n-major, k-contiguous) =================
__global__ void k_prep(const float* __restrict__ W1, const float* __restrict__ W2,
                       const float* __restrict__ Wo)
{
    int idx = blockIdx.x * blockDim.x + threadIdx.x;
    if (idx < 384 * 192) {                      // W12t[n][k]
        int n = idx / 192, k = idx % 192;
        float v = (n < 192) ? W1[k * 192 + n] : W2[k * 192 + (n - 192)];
        u16 h, l; split_bf16(v, h, l);
        g_w12t_hi[idx] = __ushort_as_bfloat16(h);
        g_w12t_lo[idx] = __ushort_as_bfloat16(l);
    } else if (idx < 2 * 384 * 192) {           // Wot[n][k] = Wo^T
        int j = idx - 384 * 192;
        int n = j / 384, k = j % 384;
        float v = Wo[k * 192 + n];
        u16 h, l; split_bf16(v, h, l);
        g_wot_hi[j] = __ushort_as_bfloat16(h);
        g_wot_lo[j] = __ushort_as_bfloat16(l);
    }
}

// ================= fused kernel =================
__global__ __launch_bounds__(THREADS, 1)
void k_fused(const float* __restrict__ x, const float* __restrict__ adj,
             const float* __restrict__ a1, const float* __restrict__ a2,
             const float* __restrict__ ao, float* __restrict__ out, int nbatch)
{
    extern __shared__ char smc[];
    float* smf = (float*)smc;
    const u32 sb = smem_u32(smc);
    const int tid = threadIdx.x, wid = tid >> 5, lane = tid & 31;
    const int l4 = lane >> 2, lq = lane & 3;
    const int wm = wid % 3, wn = wid / 3;          // warp grid 3(M) x 2(N)
    const int wS = wid % 3, wB = wid / 3;          // attention: warp triple per batch
    const int b0 = blockIdx.x * 2;
    const int nb = min(2, nbatch - b0);
    const int nrows = nb * Nn;
    const long long row0 = (long long)b0 * Nn;

    float* adjs = smf + OFF_ADJ / 4;
    float* avs  = smf + OFF_AVS / 4;
    float* whs  = (float*)(smc + OFF_WHS);
    float* who  = (float*)(smc + OFF_WHO);

    // kick off first B chunk ASAP
    issue_chunk(sb + OFF_B1, g_w12t_hi, g_w12t_lo, tid, 192);
    CPC();

    // small tables
    for (int i = tid; i < Nn * Nn; i += THREADS) adjs[i] = adj[i];
    for (int i = tid; i < 1152; i += THREADS)
        avs[i] = (i < 384) ? a1[i] : (i < 768 ? a2[i - 384] : ao[i - 768]);

    // A = split(x): 48 rows x 192, pad rows zero
    for (int idx = tid; idx < 48 * 96; idx += THREADS) {
        int r = idx / 96, kp = idx % 96;
        float2 v = make_float2(0.f, 0.f);
        if (r < nrows) v = *(const float2*)(x + (row0 + r) * Fd + kp * 2);
        u16 h0,l0,h1,l1;
        split_bf16(v.x, h0, l0); split_bf16(v.y, h1, l1);
        *(u32*)(smc + OFF_AHI + r * ASTR + kp * 4) = h0 | ((u32)h1 << 16);
        *(u32*)(smc + OFF_ALO + r * ASTR + kp * 4) = l0 | ((u32)l1 << 16);
    }

    // ---------------- GEMM1: Wh = x @ [W1|W2]  (M48 x N384 x K192) ----------------
    for (int nc = 0; nc < 12; nc++) {
        int buf = nc & 1;
        __syncthreads();
        if (nc < 11) {
            issue_chunk(sb + OFF_B1 + (buf ^ 1) * 27648,
                        g_w12t_hi + (nc + 1) * 32 * 192,
                        g_w12t_lo + (nc + 1) * 32 * 192, tid, 192);
            CPC(); CPW1();
        } else CPW0();
        __syncthreads();

        float acc[6][4];
#pragma unroll
        for (int t2 = 0; t2 < 6; t2++)
#pragma unroll
            for (int q = 0; q < 4; q++) acc[t2][q] = 0.0f;

        const char* ah = smc + OFF_AHI + (wm * 16 + l4) * ASTR;
        const char* al = smc + OFF_ALO + (wm * 16 + l4) * ASTR;
        const char* bb = smc + OFF_B1 + buf * 27648 + (wn * 16 + l4) * ASTR;
#pragma unroll
        for (int kk = 0; kk < 12; kk++) {
            int kb = kk * 32 + lq * 4;
            u32 ah0 = *(const u32*)(ah + kb),            ah1 = *(const u32*)(ah + 8*ASTR + kb);
            u32 ah2 = *(const u32*)(ah + kb + 16),       ah3 = *(const u32*)(ah + 8*ASTR + kb + 16);
            u32 al0 = *(const u32*)(al + kb),            al1 = *(const u32*)(al + 8*ASTR + kb);
            u32 al2 = *(const u32*)(al + kb + 16),       al3 = *(const u32*)(al + 8*ASTR + kb + 16);
#pragma unroll
            for (int nt = 0; nt < 2; nt++) {
                const char* bp = bb + nt * 8 * ASTR;
                u32 bh0 = *(const u32*)(bp + kb),         bh1 = *(const u32*)(bp + kb + 16);
                u32 bl0 = *(const u32*)(bp + 13824 + kb), bl1 = *(const u32*)(bp + 13824 + kb + 16);
                mma_bf16(acc[0*2+nt], ah0,ah1,ah2,ah3, bh0,bh1);
                mma_bf16(acc[1*2+nt], ah0,ah1,ah2,ah3, bl0,bl1);
                mma_bf16(acc[2*2+nt], al0,al1,al2,al3, bh0,bh1);
            }
        }
        // epilogue -> whs fp32
        int r0 = wm * 16 + l4;
#pragma unroll
        for (int nt = 0; nt < 2; nt++) {
            int c = nc * 32 + wn * 16 + nt * 8 + lq * 2;
            whs[r0 * WHS_S + c]         = acc[4+nt][0] + acc[2+nt][0] + acc[nt][0];
            whs[r0 * WHS_S + c + 1]     = acc[4+nt][1] + acc[2+nt][1] + acc[nt][1];
            whs[(r0+8) * WHS_S + c]     = acc[4+nt][2] + acc[2+nt][2] + acc[nt][2];
            whs[(r0+8) * WHS_S + c + 1] = acc[4+nt][3] + acc[2+nt][3] + acc[nt][3];
        }
    }
    __syncthreads();

    // ---------------- attention 1 (heads) ----------------
    float* evb = smf + OFF_WS / 4 + wB * 1108;
    // e-dots: 88 per batch
    if (wB < nb) {
        for (int d = wS; d < 88; d += 3) {
            int h = d / 44, rem = d % 44, sd = rem / 22, i = rem % 22;
            const float* rw = whs + (wB * Nn + i) * WHS_S + h * 192;
            const float* av = avs + h * 384 + sd * 192;
            float s = 0.0f;
#pragma unroll
            for (int j = 0; j < 6; j++) s += rw[lane + 32*j] * av[lane + 32*j];
#pragma unroll
            for (int o = 16; o; o >>= 1) s += __shfl_xor_sync(0xffffffffu, s, o);
            if (lane == 0) evb[h * 48 + sd * 22 + i] = s;
        }
    }
    // zero hc pad rows (44..47)
    for (int z = tid; z < 4 * 408; z += THREADS) {
        int r = 44 + z / 408, k = z % 408;
        *(u16*)(smc + OFF_HCHI + r * HSTR + k * 2) = 0;
        *(u16*)(smc + OFF_HCLO + r * HSTR + k * 2) = 0;
    }
    __syncthreads();
    if (wB < nb && wS < 2) warp_softmax(evb + wS * 48, adjs, evb + 96 + wS * 506, lane);
    __syncthreads();
    // hc = elu(att @ Wh), split to bf16 hi/lo
    if (wB < nb) {
#pragma unroll
        for (int g = 0; g < 2; g++) {
            int cbase = wS * 128 + g * 64;
            int h = cbase / 192;
            const float* aw = evb + 96 + h * 506;
            int c = cbase + lane * 2;
            float2 wv[Nn];
#pragma unroll
            for (int j = 0; j < Nn; j++)
                wv[j] = *(const float2*)(whs + (wB * Nn + j) * WHS_S + c);
#pragma unroll 2
            for (int i = 0; i < Nn; i++) {
                const float* awr = aw + i * 23;
                float sx = 0.f, sy = 0.f;
#pragma unroll
                for (int j = 0; j < Nn; j++) { sx += awr[j] * wv[j].x; sy += awr[j] * wv[j].y; }
                sx = elu1(sx); sy = elu1(sy);
                u16 h0,l0,h1,l1;
                split_bf16(sx, h0, l0); split_bf16(sy, h1, l1);
                int r = wB * Nn + i;
                *(u32*)(smc + OFF_HCHI + r * HSTR + c * 2) = h0 | ((u32)h1 << 16);
                *(u32*)(smc + OFF_HCLO + r * HSTR + c * 2) = l0 | ((u32)l1 << 16);
            }
        }
    }
    __syncthreads();

    // ---------------- GEMM2: who = hcat @ Wo  (M48 x N192 x K384) ----------------
    issue_chunk(sb + OFF_B2, g_wot_hi, g_wot_lo, tid, 384);
    CPC();
    {
        float acc[6][4];
        for (int nc2 = 0; nc2 < 6; nc2++) {
            for (int kh = 0; kh < 2; kh++) {
                int li = nc2 * 2 + kh, buf = li & 1;
                __syncthreads();
                if (li < 11) {
                    int nn = (li + 1) / 2, nkh = (li + 1) % 2;
                    issue_chunk(sb + OFF_B2 + (buf ^ 1) * 27648,
                                g_wot_hi + nn * 32 * 384 + nkh * 192,
                                g_wot_lo + nn * 32 * 384 + nkh * 192, tid, 384);
                    CPC(); CPW1();
                } else CPW0();
                __syncthreads();

                if (kh == 0) {
#pragma unroll
                    for (int t2 = 0; t2 < 6; t2++)
#pragma unroll
                        for (int q = 0; q < 4; q++) acc[t2][q] = 0.0f;
                }
                const char* ah = smc + OFF_HCHI + (wm * 16 + l4) * HSTR + kh * 384;
                const char* al = smc + OFF_HCLO + (wm * 16 + l4) * HSTR + kh * 384;
                const char* bb = smc + OFF_B2 + buf * 27648 + (wn * 16 + l4) * ASTR;
#pragma unroll
                for (int kk = 0; kk < 12; kk++) {
                    int ka = kk * 32 + lq * 4;
                    u32 ah0 = *(const u32*)(ah + ka),       ah1 = *(const u32*)(ah + 8*HSTR + ka);
                    u32 ah2 = *(const u32*)(ah + ka + 16),  ah3 = *(const u32*)(ah + 8*HSTR + ka + 16);
                    u32 al0 = *(const u32*)(al + ka),       al1 = *(const u32*)(al + 8*HSTR + ka);
                    u32 al2 = *(const u32*)(al + ka + 16),  al3 = *(const u32*)(al + 8*HSTR + ka + 16);
#pragma unroll
                    for (int nt = 0; nt < 2; nt++) {
                        const char* bp = bb + nt * 8 * ASTR;
                        u32 bh0 = *(const u32*)(bp + ka),         bh1 = *(const u32*)(bp + ka + 16);
                        u32 bl0 = *(const u32*)(bp + 13824 + ka), bl1 = *(const u32*)(bp + 13824 + ka + 16);
                        mma_bf16(acc[0*2+nt], ah0,ah1,ah2,ah3, bh0,bh1);
                        mma_bf16(acc[1*2+nt], ah0,ah1,ah2,ah3, bl0,bl1);
                        mma_bf16(acc[2*2+nt], al0,al1,al2,al3, bh0,bh1);
                    }
                }
                if (kh == 1) {
                    int r0 = wm * 16 + l4;
#pragma unroll
                    for (int nt = 0; nt < 2; nt++) {
                        int c = nc2 * 32 + wn * 16 + nt * 8 + lq * 2;
                        who[r0 * WHO_S + c]         = acc[4+nt][0] + acc[2+nt][0] + acc[nt][0];
                        who[r0 * WHO_S + c + 1]     = acc[4+nt][1] + acc[2+nt][1] + acc[nt][1];
                        who[(r0+8) * WHO_S + c]     = acc[4+nt][2] + acc[2+nt][2] + acc[nt][2];
                        who[(r0+8) * WHO_S + c + 1] = acc[4+nt][3] + acc[2+nt][3] + acc[nt][3];
                    }
                }
            }
        }
    }
    __syncthreads();

    // ---------------- attention 2 (output) + elu + residual ----------------
    if (wB < nb) {
        for (int d = wS; d < 44; d += 3) {
            int sd = d / 22, i = d % 22;
            const float* rw = who + (wB * Nn + i) * WHO_S;
            const float* av = avs + 768 + sd * 192;
            float s = 0.0f;
#pragma unroll
            for (int j = 0; j < 6; j++) s += rw[lane + 32*j] * av[lane + 32*j];
#pragma unroll
            for (int o = 16; o; o >>= 1) s += __shfl_xor_sync(0xffffffffu, s, o);
            if (lane == 0) evb[sd * 22 + i] = s;
        }
    }
    __syncthreads();
    if (wB < nb && wS == 0) warp_softmax(evb, adjs, evb + 96, lane);
    __syncthreads();
    if (wB < nb) {
        int c = wS * 64 + lane * 2;
        const float* aw = evb + 96;
        float2 wv[Nn];
#pragma unroll
        for (int j = 0; j < Nn; j++)
            wv[j] = *(const float2*)(who + (wB * Nn + j) * WHO_S + c);
#pragma unroll 2
        for (int i = 0; i < Nn; i++) {
            const float* awr = aw + i * 23;
            float sx = 0.f, sy = 0.f;
#pragma unroll
            for (int j = 0; j < Nn; j++) { sx += awr[j] * wv[j].x; sy += awr[j] * wv[j].y; }
            long long gi = ((long long)(b0 + wB) * Nn + i) * Fd + c;
            float2 xr = *(const float2*)(x + gi);
            float2 o;
            o.x = elu1(sx) + xr.x;
            o.y = elu1(sy) + xr.y;
            *(float2*)(out + gi) = o;
        }
    }
}

extern "C" void kernel_launch(void* const* d_in, const int* in_sizes, int n_in,
                              void* d_out, int out_size)
{
    const float* x   = (const float*)d_in[0];
    const float* adj = (const float*)d_in[1];
    const float* W1  = (const float*)d_in[2];
    const float* a1  = (const float*)d_in[3];
    const float* W2  = (const float*)d_in[4];
    const float* a2  = (const float*)d_in[5];
    const float* Wo  = (const float*)d_in[6];
    const float* ao  = (const float*)d_in[7];
    float* out = (float*)d_out;

    int nbatch = in_sizes[0] / (Nn * Fd);
    int ctas = (nbatch + 1) / 2;

    cudaFuncSetAttribute(k_fused, cudaFuncAttributeMaxDynamicSharedMemorySize, SMEM_TOTAL);

    k_prep<<<(2 * 384 * 192 + 255) / 256, 256>>>(W1, W2, Wo);
    k_fused<<<ctas, THREADS, SMEM_TOTAL>>>(x, adj, a1, a2, ao, out, nbatch);
}

// round 5
// speedup vs baseline: 2.0028x; 2.0028x over previous
#include <cuda_runtime.h>
#include <cuda_bf16.h>

#define Nn 22
#define Fd 192
#define NB4 4
#define MR 96
#define THREADS 256
#define NBATCH_MAX 16384
#define TROWS (NBATCH_MAX*Nn)

typedef unsigned int u32;
typedef unsigned short u16;

// ---- SMEM layout (bytes) ----
#define OFF_ADJ 0            // 484 f
#define OFF_AVS 1952         // 768 f
#define OFF_WS  5024         // 4 x 550 f
#define OFF_A   13824
#define ASTR    400          // 96 rows x 192 bf16 (400B stride: bank-spread, 16B align)
#define OFF_AHI OFF_A
#define OFF_ALO (OFF_A + 38400)
#define OFF_B   90624        // dbuf: per buf hi plane 15360 + lo plane 15360
#define BSTR    80           // 192 rows x 32 bf16
#define BPL     15360
#define BBUF    30720
#define OFF_WHS 152064       // 96 x 193 fp32
#define WS_S    193
#define SMEM_TOTAL 226176

// ---- device-global scratch (sanctioned path) ----
static __device__ __nv_bfloat16 g_hc_hi[(long long)TROWS*384];
static __device__ __nv_bfloat16 g_hc_lo[(long long)TROWS*384];
static __device__ __nv_bfloat16 g_w12t_hi[384*192];
static __device__ __nv_bfloat16 g_w12t_lo[384*192];
static __device__ __nv_bfloat16 g_wot_hi[192*384];
static __device__ __nv_bfloat16 g_wot_lo[192*384];

// ---- helpers ----
__device__ __forceinline__ u32 smem_u32(const void* p){
    u32 a;
    asm("{ .reg .u64 t; cvta.to.shared.u64 t, %1; cvt.u32.u64 %0, t; }" : "=r"(a) : "l"(p));
    return a;
}
__device__ __forceinline__ void split_bf16(float v, u16& h, u16& l){
    __nv_bfloat16 hb = __float2bfloat16(v);
    float hf = __bfloat162float(hb);
    __nv_bfloat16 lb = __float2bfloat16(v - hf);
    h = __bfloat16_as_ushort(hb);
    l = __bfloat16_as_ushort(lb);
}
__device__ __forceinline__ float elu1(float v){ return (v > 0.0f) ? v : (__expf(v) - 1.0f); }

#define CPA16(sa, g) asm volatile("cp.async.cg.shared.global [%0], [%1], 16;" :: "r"((u32)(sa)), "l"(g) : "memory")
#define CPC()  asm volatile("cp.async.commit_group;" ::: "memory")
#define CPW1() asm volatile("cp.async.wait_group 1;" ::: "memory")
#define CPW0() asm volatile("cp.async.wait_group 0;" ::: "memory")

__device__ __forceinline__ void mma_bf16(float* c, u32 a0,u32 a1,u32 a2,u32 a3, u32 b0,u32 b1){
    asm volatile("mma.sync.aligned.m16n8k16.row.col.f32.bf16.bf16.f32 "
        "{%0,%1,%2,%3}, {%4,%5,%6,%7}, {%8,%9}, {%0,%1,%2,%3};"
        : "+f"(c[0]),"+f"(c[1]),"+f"(c[2]),"+f"(c[3])
        : "r"(a0),"r"(a1),"r"(a2),"r"(a3),"r"(b0),"r"(b1));
}

__device__ __forceinline__ void warp_softmax(const float* __restrict__ ev, const float* __restrict__ adjs,
                                             float* __restrict__ attw, int lane)
{
    if (lane < Nn) {
        int i = lane;
        float esrc = ev[i];
        float vals[Nn];
        float mx = -1e30f;
#pragma unroll
        for (int j = 0; j < Nn; j++) {
            if (adjs[i * Nn + j] != 0.0f) {
                float v = esrc + ev[Nn + j];
                v = (v > 0.0f) ? v : 0.2f * v;
                vals[j] = v;
                mx = fmaxf(mx, v);
            } else vals[j] = -1e30f;
        }
        float ssum = 0.0f;
#pragma unroll
        for (int j = 0; j < Nn; j++) {
            float e = (vals[j] > -1e29f) ? __expf(vals[j] - mx) : 0.0f;
            vals[j] = e; ssum += e;
        }
        float inv = 1.0f / ssum;
#pragma unroll
        for (int j = 0; j < Nn; j++) attw[i * 23 + j] = vals[j] * inv;
    }
}

// stream one B chunk: 192 n-rows x 32 k (hi+lo) via cp.async 16B
__device__ __forceinline__ void issue_b(u32 dst, const __nv_bfloat16* gh, const __nv_bfloat16* gl,
                                        int tid, int rs)
{
#pragma unroll
    for (int q = 0; q < 6; q++) {
        int lin = tid + THREADS * q;        // 0..1535
        int plane = lin / 768;
        int rem = lin - plane * 768;
        int row = rem >> 2, piece = rem & 3;
        const __nv_bfloat16* src = (plane ? gl : gh) + row * rs + piece * 8;
        CPA16(dst + plane * BPL + row * BSTR + piece * 16, src);
    }
}

// GEMM mainloop over 6 k-chunks against resident A; acc[3][6][4] in regs
__device__ __forceinline__ void gemm6(char* smc, u32 sb, float acc[3][6][4],
                                      const __nv_bfloat16* bh0, const __nv_bfloat16* bl0, int rs,
                                      int tid, int wm, int wn, int l4, int lq)
{
    issue_b(sb + OFF_B, bh0, bl0, tid, rs);
    CPC();
    for (int kc = 0; kc < 6; kc++) {
        int buf = kc & 1;
        __syncthreads();
        if (kc < 5) {
            issue_b(sb + OFF_B + (buf ^ 1) * BBUF, bh0 + (kc + 1) * 32, bl0 + (kc + 1) * 32, tid, rs);
            CPC(); CPW1();
        } else CPW0();
        __syncthreads();

        const char* Ah = smc + OFF_AHI + (wm * 48 + l4) * ASTR + kc * 64;
        const char* Al = smc + OFF_ALO + (wm * 48 + l4) * ASTR + kc * 64;
        const char* Bh = smc + OFF_B + buf * BBUF + (wn * 48 + l4) * BSTR;
        const char* Bl = Bh + BPL;
#pragma unroll
        for (int s = 0; s < 2; s++) {
            int kb = s * 32 + lq * 4;
            u32 ahr[3][4], alr[3][4];
#pragma unroll
            for (int mt = 0; mt < 3; mt++) {
                const char* pa = Ah + mt * 16 * ASTR;
                ahr[mt][0] = *(const u32*)(pa + kb);
                ahr[mt][1] = *(const u32*)(pa + 8 * ASTR + kb);
                ahr[mt][2] = *(const u32*)(pa + kb + 16);
                ahr[mt][3] = *(const u32*)(pa + 8 * ASTR + kb + 16);
                const char* pl = Al + mt * 16 * ASTR;
                alr[mt][0] = *(const u32*)(pl + kb);
                alr[mt][1] = *(const u32*)(pl + 8 * ASTR + kb);
                alr[mt][2] = *(const u32*)(pl + kb + 16);
                alr[mt][3] = *(const u32*)(pl + 8 * ASTR + kb + 16);
            }
            u32 bhr[6][2], blr[6][2];
#pragma unroll
            for (int nt = 0; nt < 6; nt++) {
                const char* pb = Bh + nt * 8 * BSTR;
                bhr[nt][0] = *(const u32*)(pb + kb);
                bhr[nt][1] = *(const u32*)(pb + kb + 16);
                const char* pbl = Bl + nt * 8 * BSTR;
                blr[nt][0] = *(const u32*)(pbl + kb);
                blr[nt][1] = *(const u32*)(pbl + kb + 16);
            }
#pragma unroll
            for (int mt = 0; mt < 3; mt++)
#pragma unroll
                for (int nt = 0; nt < 6; nt++) {
                    mma_bf16(acc[mt][nt], ahr[mt][0],ahr[mt][1],ahr[mt][2],ahr[mt][3], bhr[nt][0],bhr[nt][1]);
                    mma_bf16(acc[mt][nt], ahr[mt][0],ahr[mt][1],ahr[mt][2],ahr[mt][3], blr[nt][0],blr[nt][1]);
                    mma_bf16(acc[mt][nt], alr[mt][0],alr[mt][1],alr[mt][2],alr[mt][3], bhr[nt][0],bhr[nt][1]);
                }
        }
    }
}

// ================= prep =================
__global__ void k_prep(const float* __restrict__ W1, const float* __restrict__ W2,
                       const float* __restrict__ Wo)
{
    int idx = blockIdx.x * blockDim.x + threadIdx.x;
    if (idx < 384 * 192) {
        int n = idx / 192, k = idx % 192;
        float v = (n < 192) ? W1[k * 192 + n] : W2[k * 192 + (n - 192)];
        u16 h, l; split_bf16(v, h, l);
        g_w12t_hi[idx] = __ushort_as_bfloat16(h);
        g_w12t_lo[idx] = __ushort_as_bfloat16(l);
    } else if (idx < 2 * 384 * 192) {
        int j = idx - 384 * 192;
        int n = j / 384, k = j % 384;
        float v = Wo[k * 192 + n];
        u16 h, l; split_bf16(v, h, l);
        g_wot_hi[j] = __ushort_as_bfloat16(h);
        g_wot_lo[j] = __ushort_as_bfloat16(l);
    }
}

// ================= K1: GEMM1 (per head) + head attention -> g_hc =================
__global__ __launch_bounds__(THREADS, 1)
void k1(const float* __restrict__ x, const float* __restrict__ adj,
        const float* __restrict__ a1, const float* __restrict__ a2, int nbatch)
{
    extern __shared__ char smc[];
    float* smf = (float*)smc;
    const u32 sb = smem_u32(smc);
    const int tid = threadIdx.x, wid = tid >> 5, lane = tid & 31;
    const int l4 = lane >> 2, lq = lane & 3;
    const int wm = wid & 1, wn = wid >> 1;
    const int wb = wid >> 1, sd = wid & 1;     // attention roles
    const int b0 = blockIdx.x * NB4;
    const int nb = min(NB4, nbatch - b0);
    const int nrows = nb * Nn;
    const long long row0 = (long long)b0 * Nn;

    float* adjs = smf + OFF_ADJ / 4;
    float* avs  = smf + OFF_AVS / 4;
    float* whs  = (float*)(smc + OFF_WHS);

    for (int i = tid; i < Nn * Nn; i += THREADS) adjs[i] = adj[i];
    for (int i = tid; i < 768; i += THREADS) avs[i] = (i < 384) ? a1[i] : a2[i - 384];

    // A = split(x): 96 rows x 192
    for (int idx = tid; idx < MR * 96; idx += THREADS) {
        int r = idx / 96, kp = idx % 96;
        float2 v = make_float2(0.f, 0.f);
        if (r < nrows) v = *(const float2*)(x + (row0 + r) * Fd + kp * 2);
        u16 h0,l0,h1,l1;
        split_bf16(v.x, h0, l0); split_bf16(v.y, h1, l1);
        *(u32*)(smc + OFF_AHI + r * ASTR + kp * 4) = h0 | ((u32)h1 << 16);
        *(u32*)(smc + OFF_ALO + r * ASTR + kp * 4) = l0 | ((u32)l1 << 16);
    }

    for (int h = 0; h < 2; h++) {
        float acc[3][6][4];
#pragma unroll
        for (int mt = 0; mt < 3; mt++)
#pragma unroll
            for (int nt = 0; nt < 6; nt++)
#pragma unroll
                for (int q = 0; q < 4; q++) acc[mt][nt][q] = 0.0f;

        gemm6(smc, sb, acc, g_w12t_hi + h * 192 * 192, g_w12t_lo + h * 192 * 192, 192,
              tid, wm, wn, l4, lq);

        __syncthreads();
#pragma unroll
        for (int mt = 0; mt < 3; mt++)
#pragma unroll
            for (int nt = 0; nt < 6; nt++) {
                int r = wm * 48 + mt * 16 + l4, c = wn * 48 + nt * 8 + lq * 2;
                whs[r * WS_S + c]           = acc[mt][nt][0];
                whs[r * WS_S + c + 1]       = acc[mt][nt][1];
                whs[(r + 8) * WS_S + c]     = acc[mt][nt][2];
                whs[(r + 8) * WS_S + c + 1] = acc[mt][nt][3];
            }
        __syncthreads();

        // attention head h: warp (wb, sd)
        float* ev   = smf + OFF_WS / 4 + wb * 550;
        float* attw = ev + 44;
        if (wb < nb) {
            const float* av = avs + h * 384 + sd * 192;
            for (int i = 0; i < Nn; i++) {
                const float* rw = whs + (wb * Nn + i) * WS_S;
                float s = 0.0f;
#pragma unroll
                for (int j = 0; j < 6; j++) s += rw[lane + 32 * j] * av[lane + 32 * j];
#pragma unroll
                for (int o = 16; o; o >>= 1) s += __shfl_xor_sync(0xffffffffu, s, o);
                if (lane == 0) ev[sd * Nn + i] = s;
            }
        }
        __syncthreads();
        if (wb < nb && sd == 0) warp_softmax(ev, adjs, attw, lane);
        __syncthreads();
        if (wb < nb) {
#pragma unroll
            for (int p = 0; p < 3; p++) {
                int c = sd * 96 + p * 32 + lane;
                float wv[Nn];
#pragma unroll
                for (int j = 0; j < Nn; j++) wv[j] = whs[(wb * Nn + j) * WS_S + c];
#pragma unroll 2
                for (int i = 0; i < Nn; i++) {
                    const float* aw = attw + i * 23;
                    float s = 0.0f;
#pragma unroll
                    for (int j = 0; j < Nn; j++) s += aw[j] * wv[j];
                    s = elu1(s);
                    u16 hh, ll; split_bf16(s, hh, ll);
                    long long gi = ((row0 + wb * Nn + i)) * 384 + h * 192 + c;
                    g_hc_hi[gi] = __ushort_as_bfloat16(hh);
                    g_hc_lo[gi] = __ushort_as_bfloat16(ll);
                }
            }
        }
        __syncthreads();
    }
}

// ================= K2: GEMM2 (K=384) + output attention + residual =================
__global__ __launch_bounds__(THREADS, 1)
void k2(const float* __restrict__ x, const float* __restrict__ adj,
        const float* __restrict__ ao, float* __restrict__ out, int nbatch)
{
    extern __shared__ char smc[];
    float* smf = (float*)smc;
    const u32 sb = smem_u32(smc);
    const int tid = threadIdx.x, wid = tid >> 5, lane = tid & 31;
    const int l4 = lane >> 2, lq = lane & 3;
    const int wm = wid & 1, wn = wid >> 1;
    const int wb = wid >> 1, sd = wid & 1;
    const int b0 = blockIdx.x * NB4;
    const int nb = min(NB4, nbatch - b0);
    const int nrows = nb * Nn;
    const long long row0 = (long long)b0 * Nn;

    float* adjs = smf + OFF_ADJ / 4;
    float* avs  = smf + OFF_AVS / 4;
    float* who  = (float*)(smc + OFF_WHS);

    for (int i = tid; i < Nn * Nn; i += THREADS) adjs[i] = adj[i];
    for (int i = tid; i < 384; i += THREADS) avs[i] = ao[i];

    float acc[3][6][4];
#pragma unroll
    for (int mt = 0; mt < 3; mt++)
#pragma unroll
        for (int nt = 0; nt < 6; nt++)
#pragma unroll
            for (int q = 0; q < 4; q++) acc[mt][nt][q] = 0.0f;

    for (int kh = 0; kh < 2; kh++) {
        __syncthreads();   // prior A reads complete before overwrite
        // load A half from g_hc (pre-split)
        for (int idx = tid; idx < 2 * MR * 24; idx += THREADS) {
            int plane = idx / (MR * 24);
            int rem = idx - plane * (MR * 24);
            int r = rem / 24, q = rem % 24;
            uint4 v = make_uint4(0, 0, 0, 0);
            if (r < nrows) {
                const __nv_bfloat16* src = (plane ? g_hc_lo : g_hc_hi) + (row0 + r) * 384 + kh * 192 + q * 8;
                v = *(const uint4*)src;
            }
            *(uint4*)(smc + (plane ? OFF_ALO : OFF_AHI) + r * ASTR + q * 16) = v;
        }
        gemm6(smc, sb, acc, g_wot_hi + kh * 192, g_wot_lo + kh * 192, 384,
              tid, wm, wn, l4, lq);
    }

    __syncthreads();
#pragma unroll
    for (int mt = 0; mt < 3; mt++)
#pragma unroll
        for (int nt = 0; nt < 6; nt++) {
            int r = wm * 48 + mt * 16 + l4, c = wn * 48 + nt * 8 + lq * 2;
            who[r * WS_S + c]           = acc[mt][nt][0];
            who[r * WS_S + c + 1]       = acc[mt][nt][1];
            who[(r + 8) * WS_S + c]     = acc[mt][nt][2];
            who[(r + 8) * WS_S + c + 1] = acc[mt][nt][3];
        }
    __syncthreads();

    float* ev   = smf + OFF_WS / 4 + wb * 550;
    float* attw = ev + 44;
    if (wb < nb) {
        const float* av = avs + sd * 192;
        for (int i = 0; i < Nn; i++) {
            const float* rw = who + (wb * Nn + i) * WS_S;
            float s = 0.0f;
#pragma unroll
            for (int j = 0; j < 6; j++) s += rw[lane + 32 * j] * av[lane + 32 * j];
#pragma unroll
            for (int o = 16; o; o >>= 1) s += __shfl_xor_sync(0xffffffffu, s, o);
            if (lane == 0) ev[sd * Nn + i] = s;
        }
    }
    __syncthreads();
    if (wb < nb && sd == 0) warp_softmax(ev, adjs, attw, lane);
    __syncthreads();
    if (wb < nb) {
#pragma unroll
        for (int p = 0; p < 3; p++) {
            int c = sd * 96 + p * 32 + lane;
            float wv[Nn];
#pragma unroll
            for (int j = 0; j < Nn; j++) wv[j] = who[(wb * Nn + j) * WS_S + c];
#pragma unroll 2
            for (int i = 0; i < Nn; i++) {
                const float* aw = attw + i * 23;
                float s = 0.0f;
#pragma unroll
                for (int j = 0; j < Nn; j++) s += aw[j] * wv[j];
                long long gi = (row0 + wb * Nn + i) * Fd + c;
                out[gi] = elu1(s) + x[gi];
            }
        }
    }
}

extern "C" void kernel_launch(void* const* d_in, const int* in_sizes, int n_in,
                              void* d_out, int out_size)
{
    const float* x   = (const float*)d_in[0];
    const float* adj = (const float*)d_in[1];
    const float* W1  = (const float*)d_in[2];
    const float* a1  = (const float*)d_in[3];
    const float* W2  = (const float*)d_in[4];
    const float* a2  = (const float*)d_in[5];
    const float* Wo  = (const float*)d_in[6];
    const float* ao  = (const float*)d_in[7];
    float* out = (float*)d_out;

    int nbatch = in_sizes[0] / (Nn * Fd);
    int ctas = (nbatch + NB4 - 1) / NB4;

    cudaFuncSetAttribute(k1, cudaFuncAttributeMaxDynamicSharedMemorySize, SMEM_TOTAL);
    cudaFuncSetAttribute(k2, cudaFuncAttributeMaxDynamicSharedMemorySize, SMEM_TOTAL);

    k_prep<<<(2 * 384 * 192 + 255) / 256, 256>>>(W1, W2, Wo);
    k1<<<ctas, THREADS, SMEM_TOTAL>>>(x, adj, a1, a2, nbatch);
    k2<<<ctas, THREADS, SMEM_TOTAL>>>(x, adj, ao, out, nbatch);
}